// round 1
// baseline (speedup 1.0000x reference)
#include <cuda_runtime.h>
#include <cstdint>
#include <cstddef>

#define B_   4
#define S_   4096
#define D_   2048
#define E_   64
#define N_   (B_*S_)          // 16384 tokens
#define TM   64               // tokens per block
#define DK   64               // D-chunk
#define NBLK (N_/TM)          // 256 blocks

// Deterministic aux-loss partials (no atomics => bitwise-stable across runs)
__device__ float g_load_part[NBLK][E_];
__device__ float g_z_part[NBLK];

__device__ __forceinline__ unsigned long long pack2(float lo, float hi) {
    unsigned long long r;
    asm("mov.b64 %0, {%1, %2};" : "=l"(r) : "r"(__float_as_uint(lo)), "r"(__float_as_uint(hi)));
    return r;
}
__device__ __forceinline__ void unpack2(unsigned long long v, float &lo, float &hi) {
    unsigned int a, b;
    asm("mov.b64 {%0, %1}, %2;" : "=r"(a), "=r"(b) : "l"(v));
    lo = __uint_as_float(a); hi = __uint_as_float(b);
}
__device__ __forceinline__ void ffma2(unsigned long long &d, unsigned long long a, unsigned long long b) {
    asm("fma.rn.f32x2 %0, %1, %2, %3;" : "=l"(d) : "l"(a), "l"(b), "l"(d));
}

__global__ void __launch_bounds__(128) router_main(
    const float* __restrict__ x, const float* __restrict__ W,
    const float* __restrict__ gamma, const float* __restrict__ beta,
    const float* __restrict__ temp,
    float* __restrict__ out_rw, float* __restrict__ out_disp)
{
    // smem: x-tile [64][64] + W-tile [64][65 padded]; epilogue tile [64][68] aliases it
    __shared__ float smem_all[TM*DK + E_*(DK+1)];
    __shared__ float s_exl[4][E_];
    __shared__ float s_z[4];
    float* sx = smem_all;            // [t][k], row 64
    float* sw = smem_all + TM*DK;    // [e][k], row 65 (pad kills bank conflicts)

    const int tid = threadIdx.x;
    const int blk = blockIdx.x;
    const int gt0 = blk * TM;
    const int tx  = tid & 15;        // expert group
    const int ty  = tid >> 4;        // token group
    const int e0  = tx * 4;
    const int t0  = ty * 8;

    unsigned long long acc[4][4];    // [token-pair][expert], f32x2 packed
    #pragma unroll
    for (int p = 0; p < 4; p++)
        #pragma unroll
        for (int i = 0; i < 4; i++) acc[p][i] = 0ull;

    // fill mapping: kq = tx (16 float4 columns), row = 8*p + ty
    float4 px[8], pw[8];
    #pragma unroll
    for (int p = 0; p < 8; p++) {
        const int r = p*8 + ty;
        px[p] = *(const float4*)&x[(size_t)(gt0 + r) * D_ + 4*tx];
        pw[p] = *(const float4*)&W[(size_t)r * D_ + 4*tx];
    }

    for (int c = 0; c < D_/DK; c++) {
        // stage registers -> smem
        #pragma unroll
        for (int p = 0; p < 8; p++) {
            const int r = p*8 + ty;
            *(float4*)&sx[r*DK + 4*tx] = px[p];
            const int wb = r*(DK+1) + 4*tx;
            sw[wb+0] = pw[p].x; sw[wb+1] = pw[p].y; sw[wb+2] = pw[p].z; sw[wb+3] = pw[p].w;
        }
        __syncthreads();

        // prefetch next chunk (in flight during compute)
        if (c + 1 < D_/DK) {
            const int kb = (c+1) * DK;
            #pragma unroll
            for (int p = 0; p < 8; p++) {
                const int r = p*8 + ty;
                px[p] = *(const float4*)&x[(size_t)(gt0 + r) * D_ + kb + 4*tx];
                pw[p] = *(const float4*)&W[(size_t)r * D_ + kb + 4*tx];
            }
        }

        // compute: 64 k, 2 at a time (packed f32x2 over token pairs)
        #pragma unroll 4
        for (int kk = 0; kk < DK; kk += 2) {
            float2 xa[8];
            #pragma unroll
            for (int i = 0; i < 8; i++)
                xa[i] = *(const float2*)&sx[(t0 + i)*DK + kk];
            #pragma unroll
            for (int j = 0; j < 2; j++) {
                unsigned long long xp[4];
                #pragma unroll
                for (int p = 0; p < 4; p++)
                    xp[p] = pack2(j ? xa[2*p].y : xa[2*p].x,
                                  j ? xa[2*p+1].y : xa[2*p+1].x);
                #pragma unroll
                for (int i = 0; i < 4; i++) {
                    const float w = sw[(e0 + i)*(DK+1) + kk + j];
                    const unsigned long long wp = pack2(w, w);
                    #pragma unroll
                    for (int p = 0; p < 4; p++) ffma2(acc[p][i], xp[p], wp);
                }
            }
        }
        __syncthreads();
    }

    // ---- epilogue: dump logits tile [64 tokens][68 pad] ----
    float* epi = smem_all;
    #pragma unroll
    for (int p = 0; p < 4; p++)
        #pragma unroll
        for (int i = 0; i < 4; i++) {
            float lo, hi; unpack2(acc[p][i], lo, hi);
            epi[(t0 + 2*p    )*68 + e0 + i] = lo;
            epi[(t0 + 2*p + 1)*68 + e0 + i] = hi;
        }
    __syncthreads();

    const int warp = tid >> 5, lane = tid & 31;
    const float g0 = gamma[lane], g1 = gamma[lane + 32];
    const float bb0 = beta[lane], bb1 = beta[lane + 32];
    const float invt = 1.0f / (temp[0] + 1e-6f);

    for (int e = lane; e < E_; e += 32) s_exl[warp][e] = 0.0f;

    float zacc = 0.0f;
    for (int t = warp*16; t < warp*16 + 16; t++) {
        const float v0 = epi[t*68 + lane];
        const float v1 = epi[t*68 + lane + 32];
        // LayerNorm over experts (two-pass, biased var)
        float s = v0 + v1;
        #pragma unroll
        for (int o = 16; o; o >>= 1) s += __shfl_xor_sync(~0u, s, o);
        const float mu = s * (1.0f/64.0f);
        const float d0 = v0 - mu, d1 = v1 - mu;
        float q = d0*d0 + d1*d1;
        #pragma unroll
        for (int o = 16; o; o >>= 1) q += __shfl_xor_sync(~0u, q, o);
        const float inv = rsqrtf(q * (1.0f/64.0f) + 1e-5f);
        const float y0 = d0*inv*g0 + bb0;
        const float y1 = d1*inv*g1 + bb1;
        zacc += y0*y0 + y1*y1;
        // temperature softmax (max-subtracted)
        const float sc0 = y0*invt, sc1 = y1*invt;
        float m = fmaxf(sc0, sc1);
        #pragma unroll
        for (int o = 16; o; o >>= 1) m = fmaxf(m, __shfl_xor_sync(~0u, m, o));
        const float ex0 = __expf(sc0 - m), ex1 = __expf(sc1 - m);
        float es = ex0 + ex1;
        #pragma unroll
        for (int o = 16; o; o >>= 1) es += __shfl_xor_sync(~0u, es, o);
        const float rinv = 1.0f / es;
        const float p0 = ex0 * rinv, p1 = ex1 * rinv;
        // top-1 (tie -> lower index, matches top_k)
        float bv; int bi;
        if (p0 >= p1) { bv = p0; bi = lane; } else { bv = p1; bi = lane + 32; }
        #pragma unroll
        for (int o = 16; o; o >>= 1) {
            float ov = __shfl_xor_sync(~0u, bv, o);
            int   oi = __shfl_xor_sync(~0u, bi, o);
            if (ov > bv || (ov == bv && oi < bi)) { bv = ov; bi = oi; }
        }
        const float w1 = bv; const int i1 = bi;
        // top-2
        const float c0 = (lane      == i1) ? -1.0f : p0;
        const float c1 = (lane + 32 == i1) ? -1.0f : p1;
        if (c0 >= c1) { bv = c0; bi = lane; } else { bv = c1; bi = lane + 32; }
        #pragma unroll
        for (int o = 16; o; o >>= 1) {
            float ov = __shfl_xor_sync(~0u, bv, o);
            int   oi = __shfl_xor_sync(~0u, bi, o);
            if (ov > bv || (ov == bv && oi < bi)) { bv = ov; bi = oi; }
        }
        const float w2 = bv; const int i2 = bi;

        const size_t base = (size_t)(gt0 + t) * E_;
        out_rw[base + lane]      = p0;
        out_rw[base + lane + 32] = p1;
        out_disp[base + lane]      = (lane == i1 || lane == i2)           ? p0 : 0.0f;
        out_disp[base + lane + 32] = (lane + 32 == i1 || lane + 32 == i2) ? p1 : 0.0f;

        if (i1 == lane)           s_exl[warp][lane]      += w1;
        else if (i1 == lane + 32) s_exl[warp][lane + 32] += w1;
        if (i2 == lane)           s_exl[warp][lane]      += w2;
        else if (i2 == lane + 32) s_exl[warp][lane + 32] += w2;
    }
    #pragma unroll
    for (int o = 16; o; o >>= 1) zacc += __shfl_xor_sync(~0u, zacc, o);
    if (lane == 0) s_z[warp] = zacc;
    __syncthreads();
    if (tid < E_)
        g_load_part[blk][tid] = s_exl[0][tid] + s_exl[1][tid] + s_exl[2][tid] + s_exl[3][tid];
    if (tid == 0)
        g_z_part[blk] = s_z[0] + s_z[1] + s_z[2] + s_z[3];
}

// 1 block, 256 threads: deterministic fixed-order reductions for total_loss
__global__ void router_finalize(float* __restrict__ out_loss)
{
    __shared__ float sh[256];
    const int tid = threadIdx.x;

    const float z = g_z_part[tid];
    const int b = tid >> 6, e = tid & 63;
    float l = 0.0f;
    for (int k = 0; k < S_/TM; k++) l += g_load_part[b*(S_/TM) + k][e];
    l *= (1.0f / S_);                       // expert_load[b][e]

    sh[tid] = l; __syncthreads();
    for (int o = 128; o; o >>= 1) { if (tid < o) sh[tid] += sh[tid + o]; __syncthreads(); }
    const float mean = sh[0] * (1.0f/256.0f);
    __syncthreads();

    const float d = l - mean;
    sh[tid] = d * d; __syncthreads();
    for (int o = 128; o; o >>= 1) { if (tid < o) sh[tid] += sh[tid + o]; __syncthreads(); }
    const float var = sh[0] * (1.0f/255.0f);   // ddof=1
    __syncthreads();

    sh[tid] = z; __syncthreads();
    for (int o = 128; o; o >>= 1) { if (tid < o) sh[tid] += sh[tid + o]; __syncthreads(); }

    if (tid == 0) {
        const float zmean = sh[0] / (float)((size_t)N_ * E_);
        const float lb = (sqrtf(var) / mean) * 10.0f;
        out_loss[0] = 0.001f * zmean + 0.1f * lb;
    }
}

extern "C" void kernel_launch(void* const* d_in, const int* in_sizes, int n_in,
                              void* d_out, int out_size)
{
    (void)in_sizes; (void)n_in; (void)out_size;
    const float* x     = (const float*)d_in[0];
    const float* W     = (const float*)d_in[1];
    const float* gamma = (const float*)d_in[2];
    const float* beta  = (const float*)d_in[3];
    const float* temp  = (const float*)d_in[4];

    float* out  = (float*)d_out;
    float* rw   = out;                          // routing_weights [N,E]
    float* disp = out + (size_t)N_ * E_;        // dispatch        [B,S,E]
    float* loss = out + (size_t)2 * N_ * E_;    // total_loss scalar

    router_main<<<NBLK, 128>>>(x, W, gamma, beta, temp, rw, disp);
    router_finalize<<<1, 256>>>(loss);
}